// round 14
// baseline (speedup 1.0000x reference)
#include <cuda_runtime.h>
#include <cuda_bf16.h>
#include <math.h>
#include <stdint.h>

// ---------------- problem dims ----------------
#define BATCH   2
#define SEQ     2048
#define HIDDEN  2048
#define NHEADS  64
#define PDIM    64
#define IDIM    4096          // NH*P
#define NDIM    128
#define CONVD   4352          // I + 2*G*N
#define PROJD   8512          // I + CONVD + NH
#define MROWS   4096          // BATCH*SEQ

// ---------------- scratch (device globals; allocation-free rule) ----------------
__device__ __align__(16) float g_proj[(size_t)MROWS * PROJD];
__device__ __align__(16) float g_conv[(size_t)MROWS * CONVD];
__device__ __align__(16) float g_dt  [(size_t)MROWS * NHEADS];
__device__ __align__(16) float g_dA  [(size_t)MROWS * NHEADS];
__device__ __align__(16) float g_y   [(size_t)MROWS * IDIM];

// bf16 hi/lo split operands
__device__ __align__(16) __nv_bfloat16 g_hs_h [(size_t)MROWS * HIDDEN];
__device__ __align__(16) __nv_bfloat16 g_hs_l [(size_t)MROWS * HIDDEN];
__device__ __align__(16) __nv_bfloat16 g_win_h[(size_t)PROJD * HIDDEN];
__device__ __align__(16) __nv_bfloat16 g_win_l[(size_t)PROJD * HIDDEN];
__device__ __align__(16) __nv_bfloat16 g_yn_h [(size_t)MROWS * IDIM];
__device__ __align__(16) __nv_bfloat16 g_yn_l [(size_t)MROWS * IDIM];
__device__ __align__(16) __nv_bfloat16 g_wo_h [(size_t)HIDDEN * IDIM];
__device__ __align__(16) __nv_bfloat16 g_wo_l [(size_t)HIDDEN * IDIM];

// ---------------- PTX helpers (base-target safe) ----------------
__device__ __forceinline__ uint32_t smem_u32(const void* p) {
    uint32_t a;
    asm("{ .reg .u64 t; cvta.to.shared.u64 t, %1; cvt.u32.u64 %0, t; }" : "=r"(a) : "l"(p));
    return a;
}

#define CP_ASYNC16(dst, src) \
    asm volatile("cp.async.cg.shared.global [%0], [%1], 16;" :: "r"(dst), "l"(src) : "memory")
#define CP_ASYNC4(dst, src) \
    asm volatile("cp.async.ca.shared.global [%0], [%1], 4;" :: "r"(dst), "l"(src) : "memory")
#define CP_COMMIT() asm volatile("cp.async.commit_group;" ::: "memory")
#define CP_WAIT(n)  asm volatile("cp.async.wait_group %0;" :: "n"(n) : "memory")

__device__ __forceinline__ void ldsm_x4(uint32_t* r, uint32_t addr) {
    asm volatile("ldmatrix.sync.aligned.m8n8.x4.shared.b16 {%0,%1,%2,%3}, [%4];"
                 : "=r"(r[0]), "=r"(r[1]), "=r"(r[2]), "=r"(r[3]) : "r"(addr));
}

__device__ __forceinline__ void mma_bf16(float* c, const uint32_t* a, const uint32_t* b) {
    asm volatile("mma.sync.aligned.m16n8k16.row.col.f32.bf16.bf16.f32 "
                 "{%0,%1,%2,%3}, {%4,%5,%6,%7}, {%8,%9}, {%0,%1,%2,%3};"
                 : "+f"(c[0]), "+f"(c[1]), "+f"(c[2]), "+f"(c[3])
                 : "r"(a[0]), "r"(a[1]), "r"(a[2]), "r"(a[3]), "r"(b[0]), "r"(b[1]));
}

// ---------------- HMMA GEMM: C[m,n] = sum_k A[m,k]*B[n,k] via 3xBF16 split ------------
// ldc decoupled from Nn so partial-N launches can write into a wider matrix.
#define BK          32
#define STAGES      3
#define ARR_BYTES   (128 * BK * 2)
#define STG_BYTES   (4 * ARR_BYTES)
#define GEMM_SMEM   (STAGES * STG_BYTES)

__device__ __forceinline__ uint32_t swz(int r, int c4) {
    return (uint32_t)(r * 64 + ((c4 ^ ((r >> 1) & 3)) << 4));
}

template<bool GUARD_N>
__global__ __launch_bounds__(256) void gemm_mma(
    const __nv_bfloat16* __restrict__ Ah, const __nv_bfloat16* __restrict__ Al,
    const __nv_bfloat16* __restrict__ Bh, const __nv_bfloat16* __restrict__ Bl,
    float* __restrict__ C, int M, int Nn, int Kk, int ldc)
{
    extern __shared__ char smem[];
    const uint32_t sb = smem_u32(smem);
    const int tid = threadIdx.x;
    const int wid = tid >> 5;
    const int lid = tid & 31;
    const int warp_m = wid & 3;
    const int warp_n = wid >> 2;
    const int m0 = blockIdx.x * 128;
    const int n0 = blockIdx.y * 128;

    const __nv_bfloat16* srcs[4] = {Ah, Al, Bh, Bl};

    float acc[2][8][4];
#pragma unroll
    for (int i = 0; i < 2; i++)
#pragma unroll
        for (int j = 0; j < 8; j++)
#pragma unroll
            for (int q = 0; q < 4; q++) acc[i][j][q] = 0.f;

    const int KT = Kk / BK;
    const int id0 = tid, id1 = tid + 256;
    const int r0i = id0 >> 2, c40 = id0 & 3;
    const int r1i = id1 >> 2, c41 = id1 & 3;

    auto load_stage = [&](int s, int kt) {
        const uint32_t stg = sb + s * STG_BYTES;
        const size_t kb = (size_t)(kt * BK) * 2;
#pragma unroll
        for (int arr = 0; arr < 4; arr++) {
            const char* base = (const char*)srcs[arr];
            const int rbase = (arr < 2) ? m0 : n0;
            int gr0 = rbase + r0i, gr1 = rbase + r1i;
            if (GUARD_N && arr >= 2) {
                gr0 = (gr0 < Nn) ? gr0 : (Nn - 1);
                gr1 = (gr1 < Nn) ? gr1 : (Nn - 1);
            }
            CP_ASYNC16(stg + arr * ARR_BYTES + swz(r0i, c40),
                       base + (size_t)gr0 * Kk * 2 + kb + c40 * 16);
            CP_ASYNC16(stg + arr * ARR_BYTES + swz(r1i, c41),
                       base + (size_t)gr1 * Kk * 2 + kb + c41 * 16);
        }
    };

    load_stage(0, 0); CP_COMMIT();
    load_stage(1, 1); CP_COMMIT();

    const int rowin = lid & 7;
    const int mat   = lid >> 3;

    for (int kt = 0; kt < KT; kt++) {
        CP_WAIT(STAGES - 2);
        __syncthreads();

        const uint32_t stg = sb + (kt % STAGES) * STG_BYTES;
#pragma unroll
        for (int ks = 0; ks < 2; ks++) {
            uint32_t afr[2][2][4];
#pragma unroll
            for (int split = 0; split < 2; split++)
#pragma unroll
                for (int mt = 0; mt < 2; mt++) {
                    int r  = warp_m * 32 + mt * 16 + rowin + ((mat & 1) << 3);
                    int c4 = ks * 2 + (mat >> 1);
                    ldsm_x4(afr[split][mt], stg + split * ARR_BYTES + swz(r, c4));
                }
            uint32_t bfr[2][8][2];
#pragma unroll
            for (int split = 0; split < 2; split++)
#pragma unroll
                for (int ntp = 0; ntp < 4; ntp++) {
                    int n  = warp_n * 64 + ntp * 16 + rowin + ((mat >> 1) << 3);
                    int c4 = ks * 2 + (mat & 1);
                    uint32_t t[4];
                    ldsm_x4(t, stg + (2 + split) * ARR_BYTES + swz(n, c4));
                    bfr[split][ntp * 2][0]     = t[0];
                    bfr[split][ntp * 2][1]     = t[1];
                    bfr[split][ntp * 2 + 1][0] = t[2];
                    bfr[split][ntp * 2 + 1][1] = t[3];
                }
#pragma unroll
            for (int mt = 0; mt < 2; mt++)
#pragma unroll
                for (int nt = 0; nt < 8; nt++) {
                    mma_bf16(acc[mt][nt], afr[0][mt], bfr[0][nt]);
                    mma_bf16(acc[mt][nt], afr[0][mt], bfr[1][nt]);
                    mma_bf16(acc[mt][nt], afr[1][mt], bfr[0][nt]);
                }
        }

        const int knext = kt + STAGES - 1;
        if (knext < KT) load_stage(knext % STAGES, knext);
        CP_COMMIT();
    }

    const int gq  = lid >> 2;
    const int ln2 = (lid & 3) * 2;
#pragma unroll
    for (int mt = 0; mt < 2; mt++) {
        const int m = m0 + warp_m * 32 + mt * 16 + gq;
#pragma unroll
        for (int nt = 0; nt < 8; nt++) {
            const int n = n0 + warp_n * 64 + nt * 8 + ln2;
            if (!GUARD_N || n < Nn) {
                *(float2*)(C + (size_t)m * ldc + n) =
                    make_float2(acc[mt][nt][0], acc[mt][nt][1]);
                *(float2*)(C + (size_t)(m + 8) * ldc + n) =
                    make_float2(acc[mt][nt][2], acc[mt][nt][3]);
            }
        }
    }
}

// ---------------- bf16 hi/lo split conversion ----------------
__global__ __launch_bounds__(256) void split_bf16(const float* __restrict__ x,
                                                  __nv_bfloat16* __restrict__ h,
                                                  __nv_bfloat16* __restrict__ l,
                                                  size_t n4)
{
    size_t i = (size_t)blockIdx.x * 256 + threadIdx.x;
    if (i >= n4) return;
    float4 v = *(const float4*)(x + i * 4);
    __nv_bfloat16 h0 = __float2bfloat16(v.x), h1 = __float2bfloat16(v.y);
    __nv_bfloat16 h2 = __float2bfloat16(v.z), h3 = __float2bfloat16(v.w);
    __nv_bfloat16 l0 = __float2bfloat16(v.x - __bfloat162float(h0));
    __nv_bfloat16 l1 = __float2bfloat16(v.y - __bfloat162float(h1));
    __nv_bfloat16 l2 = __float2bfloat16(v.z - __bfloat162float(h2));
    __nv_bfloat16 l3 = __float2bfloat16(v.w - __bfloat162float(h3));
    __nv_bfloat162* hp = (__nv_bfloat162*)(h + i * 4);
    __nv_bfloat162* lp = (__nv_bfloat162*)(l + i * 4);
    hp[0] = __nv_bfloat162(h0, h1); hp[1] = __nv_bfloat162(h2, h3);
    lp[0] = __nv_bfloat162(l0, l1); lp[1] = __nv_bfloat162(l2, l3);
}

// ---------------- depthwise causal conv (K=4) + SiLU ----------------
__global__ __launch_bounds__(256) void conv_silu_kernel(const float* __restrict__ cw,
                                                        const float* __restrict__ cb)
{
    int c = blockIdx.x * 256 + threadIdx.x;
    int s = blockIdx.y;
    int b = blockIdx.z;
    float w0 = cw[c * 4 + 0], w1 = cw[c * 4 + 1], w2 = cw[c * 4 + 2], w3 = cw[c * 4 + 3];
    const float* base = g_proj + (size_t)(b * SEQ) * PROJD + IDIM + c;
    float acc = cb[c];
    if (s >= 3) acc = fmaf(base[(size_t)(s - 3) * PROJD], w0, acc);
    if (s >= 2) acc = fmaf(base[(size_t)(s - 2) * PROJD], w1, acc);
    if (s >= 1) acc = fmaf(base[(size_t)(s - 1) * PROJD], w2, acc);
    acc = fmaf(base[(size_t)s * PROJD], w3, acc);
    acc = acc / (1.f + expf(-acc));
    g_conv[(size_t)(b * SEQ + s) * CONVD + c] = acc;
}

// ---------------- dt/dA ----------------
__global__ __launch_bounds__(256) void dt_kernel(const float* __restrict__ dt_bias,
                                                 const float* __restrict__ A_log)
{
    int idx = blockIdx.x * 256 + threadIdx.x;
    int h = idx & (NHEADS - 1);
    int bs = idx >> 6;
    float v = g_proj[(size_t)bs * PROJD + IDIM + CONVD + h] + dt_bias[h];
    float sp = (v > 20.f) ? v : log1pf(expf(v));
    sp = fminf(fmaxf(sp, 0.f), 1e9f);
    g_dt[idx] = sp;
    g_dA[idx] = expf(-expf(A_log[h]) * sp);
}

// ---------------- sequential selective scan (pipelined loads + pipelined reduce) ----
#define NSTG   8
#define SGF    336
#define OFF_B  0
#define OFF_C  128
#define OFF_X  256
#define OFF_M  320

__global__ __launch_bounds__(512) void scan_kernel(const float* __restrict__ Dp)
{
    __shared__ __align__(16) float sbuf[NSTG * SGF];
    __shared__ float red[2][8][72];

    const int b   = blockIdx.x >> 6;
    const int h   = blockIdx.x & 63;
    const int tid = threadIdx.x;
    const int p   = tid & 63;
    const int ng  = tid >> 6;          // 0..7, uniform per warp
    const int n0  = ng * 16;

    const float* convb = g_conv + (size_t)b * SEQ * CONVD;
    const float* dtp   = g_dt  + (size_t)b * SEQ * NHEADS + h;
    const float* dAp   = g_dA  + (size_t)b * SEQ * NHEADS + h;
    float*       yb    = g_y   + (size_t)b * SEQ * IDIM + h * PDIM;
    const uint32_t sb  = smem_u32(sbuf);

    auto fill = [&](int s, int t) {
        if (t < SEQ) {
            const float* row = convb + (size_t)t * CONVD;
            const uint32_t dst = sb + (uint32_t)(s * SGF) * 4;
            if (tid < 32) {
                CP_ASYNC16(dst + OFF_B * 4 + tid * 16, row + IDIM + tid * 4);
            } else if (tid < 64) {
                CP_ASYNC16(dst + OFF_C * 4 + (tid - 32) * 16, row + IDIM + NDIM + (tid - 32) * 4);
            } else if (tid < 80) {
                CP_ASYNC16(dst + OFF_X * 4 + (tid - 64) * 16, row + h * PDIM + (tid - 64) * 4);
            } else if (tid == 80) {
                CP_ASYNC4(dst + (OFF_M + 0) * 4, dAp + (size_t)t * NHEADS);
            } else if (tid == 81) {
                CP_ASYNC4(dst + (OFF_M + 1) * 4, dtp + (size_t)t * NHEADS);
            }
        }
    };

#pragma unroll
    for (int i = 0; i < NSTG - 1; i++) { fill(i, i); CP_COMMIT(); }

    const float Dh = Dp[h];
    float st[16];
#pragma unroll
    for (int j = 0; j < 16; j++) st[j] = 0.f;
    float x_prev = 0.f;

    for (int t = 0; t < SEQ; t++) {
        CP_WAIT(NSTG - 2);
        __syncthreads();

        if (t > 0 && tid < 64) {
            const float (*rp)[72] = red[(t - 1) & 1];
            float s = rp[0][tid] + rp[1][tid] + rp[2][tid] + rp[3][tid]
                    + rp[4][tid] + rp[5][tid] + rp[6][tid] + rp[7][tid];
            yb[(size_t)(t - 1) * IDIM + tid] = fmaf(Dh, x_prev, s);
        }

        fill((t + NSTG - 1) % NSTG, t + NSTG - 1);
        CP_COMMIT();

        const float* stg = sbuf + (t % NSTG) * SGF;
        const float dAv = stg[OFF_M + 0];
        const float dtv = stg[OFF_M + 1];
        const float xv  = stg[OFF_X + p];
        const float coef = dtv * xv;
        x_prev = xv;

        float acc = 0.f;
#pragma unroll
        for (int q = 0; q < 4; q++) {
            float4 B4 = *(const float4*)(stg + OFF_B + n0 + q * 4);
            float4 C4 = *(const float4*)(stg + OFF_C + n0 + q * 4);
            float* s4 = st + q * 4;
            s4[0] = fmaf(s4[0], dAv, coef * B4.x);
            s4[1] = fmaf(s4[1], dAv, coef * B4.y);
            s4[2] = fmaf(s4[2], dAv, coef * B4.z);
            s4[3] = fmaf(s4[3], dAv, coef * B4.w);
            acc = fmaf(s4[0], C4.x, acc);
            acc = fmaf(s4[1], C4.y, acc);
            acc = fmaf(s4[2], C4.z, acc);
            acc = fmaf(s4[3], C4.w, acc);
        }
        red[t & 1][ng][p] = acc;
    }

    __syncthreads();
    if (tid < 64) {
        const float (*rp)[72] = red[(SEQ - 1) & 1];
        float s = rp[0][tid] + rp[1][tid] + rp[2][tid] + rp[3][tid]
                + rp[4][tid] + rp[5][tid] + rp[6][tid] + rp[7][tid];
        yb[(size_t)(SEQ - 1) * IDIM + tid] = fmaf(Dh, x_prev, s);
    }
}

// ---------------- y*silu(gate), RMSNorm, fused bf16 split ----------------
__global__ __launch_bounds__(256) void gate_norm_kernel(const float* __restrict__ norm_w)
{
    int bs = blockIdx.x;
    const float* gp   = g_proj + (size_t)bs * PROJD;
    const float* yrow = g_y    + (size_t)bs * IDIM;
    __nv_bfloat16* oh = g_yn_h + (size_t)bs * IDIM;
    __nv_bfloat16* ol = g_yn_l + (size_t)bs * IDIM;

    float v[16];
    float ss = 0.f;
#pragma unroll
    for (int i = 0; i < 16; i++) {
        int idx = threadIdx.x + i * 256;
        float gate = gp[idx];
        float sil = gate / (1.f + expf(-gate));
        float val = yrow[idx] * sil;
        v[i] = val;
        ss = fmaf(val, val, ss);
    }
#pragma unroll
    for (int off = 16; off; off >>= 1) ss += __shfl_xor_sync(0xffffffffu, ss, off);
    __shared__ float red[8];
    if ((threadIdx.x & 31) == 0) red[threadIdx.x >> 5] = ss;
    __syncthreads();
    float tot = 0.f;
#pragma unroll
    for (int w = 0; w < 8; w++) tot += red[w];
    float scale = rsqrtf(tot * (1.f / IDIM) + 1e-6f);
#pragma unroll
    for (int i = 0; i < 16; i++) {
        int idx = threadIdx.x + i * 256;
        float val = v[i] * scale * norm_w[idx];
        __nv_bfloat16 hb = __float2bfloat16(val);
        oh[idx] = hb;
        ol[idx] = __float2bfloat16(val - __bfloat162float(hb));
    }
}

// ---------------- launch ----------------
extern "C" void kernel_launch(void* const* d_in, const int* in_sizes, int n_in,
                              void* d_out, int out_size)
{
    const float* hs      = (const float*)d_in[0];
    const float* w_in    = (const float*)d_in[2];
    const float* conv_w  = (const float*)d_in[3];
    const float* conv_b  = (const float*)d_in[4];
    const float* dt_bias = (const float*)d_in[5];
    const float* A_log   = (const float*)d_in[6];
    const float* Dp      = (const float*)d_in[7];
    const float* norm_w  = (const float*)d_in[8];
    const float* w_out   = (const float*)d_in[9];
    float* out = (float*)d_out;

    float *proj;
    __nv_bfloat16 *hs_h, *hs_l, *win_h, *win_l, *yn_h, *yn_l, *wo_h, *wo_l;
    cudaGetSymbolAddress((void**)&proj,  g_proj);
    cudaGetSymbolAddress((void**)&hs_h,  g_hs_h);
    cudaGetSymbolAddress((void**)&hs_l,  g_hs_l);
    cudaGetSymbolAddress((void**)&win_h, g_win_h);
    cudaGetSymbolAddress((void**)&win_l, g_win_l);
    cudaGetSymbolAddress((void**)&yn_h,  g_yn_h);
    cudaGetSymbolAddress((void**)&yn_l,  g_yn_l);
    cudaGetSymbolAddress((void**)&wo_h,  g_wo_h);
    cudaGetSymbolAddress((void**)&wo_l,  g_wo_l);

    cudaFuncSetAttribute(gemm_mma<true>,
                         cudaFuncAttributeMaxDynamicSharedMemorySize, GEMM_SMEM);
    cudaFuncSetAttribute(gemm_mma<false>,
                         cudaFuncAttributeMaxDynamicSharedMemorySize, GEMM_SMEM);

    // fork-join resources (created per call; kernel_launch runs only a few times,
    // graph replays do not re-enter this function)
    cudaStream_t s1;
    cudaStreamCreateWithFlags(&s1, cudaStreamNonBlocking);
    cudaEvent_t evSplit, evA, evB;
    cudaEventCreateWithFlags(&evSplit, cudaEventDisableTiming);
    cudaEventCreateWithFlags(&evA,     cudaEventDisableTiming);
    cudaEventCreateWithFlags(&evB,     cudaEventDisableTiming);

    // stream 0: operand splits needed by GEMM1
    {
        size_t n4;
        n4 = (size_t)MROWS * HIDDEN / 4;
        split_bf16<<<(unsigned)((n4 + 255) / 256), 256>>>(hs, hs_h, hs_l, n4);
        n4 = (size_t)PROJD * HIDDEN / 4;
        split_bf16<<<(unsigned)((n4 + 255) / 256), 256>>>(w_in, win_h, win_l, n4);
    }
    cudaEventRecord(evSplit, 0);

    // stream s1: w_out split (overlaps GEMM1a on stream 0)
    cudaStreamWaitEvent(s1, evSplit, 0);
    {
        size_t n4 = (size_t)HIDDEN * IDIM / 4;
        split_bf16<<<(unsigned)((n4 + 255) / 256), 256, 0, s1>>>(w_out, wo_h, wo_l, n4);
    }

    // stream 0: scan-path GEMM1a (cols 4096..8511)
    {
        const int NA = PROJD - IDIM;                // 4416
        dim3 g1a(MROWS / 128, (NA + 127) / 128);    // 32 x 35
        gemm_mma<true><<<g1a, 256, GEMM_SMEM>>>(hs_h, hs_l,
                                                win_h + (size_t)IDIM * HIDDEN,
                                                win_l + (size_t)IDIM * HIDDEN,
                                                proj + IDIM, MROWS, NA, HIDDEN, PROJD);
    }
    cudaEventRecord(evA, 0);

    // stream s1: gate-part GEMM1b starts only AFTER GEMM1a completes,
    // so it overlaps conv->dt->scan (not GEMM1a).
    cudaStreamWaitEvent(s1, evA, 0);
    {
        dim3 g1b(MROWS / 128, IDIM / 128);          // 32 x 32
        gemm_mma<false><<<g1b, 256, GEMM_SMEM, s1>>>(hs_h, hs_l, win_h, win_l,
                                                     proj, MROWS, IDIM, HIDDEN, PROJD);
    }
    cudaEventRecord(evB, s1);

    // stream 0: conv -> dt -> scan (concurrent with GEMM1b)
    conv_silu_kernel<<<dim3(CONVD / 256, SEQ, BATCH), 256>>>(conv_w, conv_b);
    dt_kernel<<<(MROWS * NHEADS) / 256, 256>>>(dt_bias, A_log);
    scan_kernel<<<BATCH * NHEADS, 512>>>(Dp);

    // join: gate_norm needs gate (s1) + y (stream 0)
    cudaStreamWaitEvent(0, evB, 0);
    gate_norm_kernel<<<MROWS, 256>>>(norm_w);

    // out-projection (M=4096, N=2048, K=4096)
    dim3 g2(MROWS / 128, HIDDEN / 128);
    gemm_mma<false><<<g2, 256, GEMM_SMEM>>>(yn_h, yn_l, wo_h, wo_l,
                                            out, MROWS, HIDDEN, IDIM, HIDDEN);
}

// round 15
// speedup vs baseline: 1.0201x; 1.0201x over previous
#include <cuda_runtime.h>
#include <cuda_bf16.h>
#include <math.h>
#include <stdint.h>

// ---------------- problem dims ----------------
#define BATCH   2
#define SEQ     2048
#define HIDDEN  2048
#define NHEADS  64
#define PDIM    64
#define IDIM    4096          // NH*P
#define NDIM    128
#define CONVD   4352          // I + 2*G*N
#define PROJD   8512          // I + CONVD + NH
#define MROWS   4096          // BATCH*SEQ

// ---------------- scratch (device globals; allocation-free rule) ----------------
__device__ __align__(16) float g_proj[(size_t)MROWS * PROJD];
__device__ __align__(16) float g_conv[(size_t)MROWS * CONVD];
__device__ __align__(16) float g_dt  [(size_t)MROWS * NHEADS];
__device__ __align__(16) float g_dA  [(size_t)MROWS * NHEADS];
__device__ __align__(16) float g_y   [(size_t)MROWS * IDIM];

// bf16 hi/lo split operands
__device__ __align__(16) __nv_bfloat16 g_hs_h [(size_t)MROWS * HIDDEN];
__device__ __align__(16) __nv_bfloat16 g_hs_l [(size_t)MROWS * HIDDEN];
__device__ __align__(16) __nv_bfloat16 g_win_h[(size_t)PROJD * HIDDEN];
__device__ __align__(16) __nv_bfloat16 g_win_l[(size_t)PROJD * HIDDEN];
__device__ __align__(16) __nv_bfloat16 g_yn_h [(size_t)MROWS * IDIM];
__device__ __align__(16) __nv_bfloat16 g_yn_l [(size_t)MROWS * IDIM];
__device__ __align__(16) __nv_bfloat16 g_wo_h [(size_t)HIDDEN * IDIM];
__device__ __align__(16) __nv_bfloat16 g_wo_l [(size_t)HIDDEN * IDIM];

// ---------------- PTX helpers (base-target safe) ----------------
__device__ __forceinline__ uint32_t smem_u32(const void* p) {
    uint32_t a;
    asm("{ .reg .u64 t; cvta.to.shared.u64 t, %1; cvt.u32.u64 %0, t; }" : "=r"(a) : "l"(p));
    return a;
}

#define CP_ASYNC16(dst, src) \
    asm volatile("cp.async.cg.shared.global [%0], [%1], 16;" :: "r"(dst), "l"(src) : "memory")
#define CP_ASYNC4(dst, src) \
    asm volatile("cp.async.ca.shared.global [%0], [%1], 4;" :: "r"(dst), "l"(src) : "memory")
#define CP_COMMIT() asm volatile("cp.async.commit_group;" ::: "memory")
#define CP_WAIT(n)  asm volatile("cp.async.wait_group %0;" :: "n"(n) : "memory")

__device__ __forceinline__ void ldsm_x4(uint32_t* r, uint32_t addr) {
    asm volatile("ldmatrix.sync.aligned.m8n8.x4.shared.b16 {%0,%1,%2,%3}, [%4];"
                 : "=r"(r[0]), "=r"(r[1]), "=r"(r[2]), "=r"(r[3]) : "r"(addr));
}

__device__ __forceinline__ void mma_bf16(float* c, const uint32_t* a, const uint32_t* b) {
    asm volatile("mma.sync.aligned.m16n8k16.row.col.f32.bf16.bf16.f32 "
                 "{%0,%1,%2,%3}, {%4,%5,%6,%7}, {%8,%9}, {%0,%1,%2,%3};"
                 : "+f"(c[0]), "+f"(c[1]), "+f"(c[2]), "+f"(c[3])
                 : "r"(a[0]), "r"(a[1]), "r"(a[2]), "r"(a[3]), "r"(b[0]), "r"(b[1]));
}

// ---------------- HMMA GEMM: C[m,n] = sum_k A[m,k]*B[n,k] via 3xBF16 split ------------
// ldc decoupled from Nn so partial-N launches can write into a wider matrix.
// __launch_bounds__(256, 2): 2 CTAs/SM (192KB smem, regs capped at 128) so one CTA's
// HMMAs cover the other's barrier/ldsm shadows.
#define BK          32
#define STAGES      3
#define ARR_BYTES   (128 * BK * 2)
#define STG_BYTES   (4 * ARR_BYTES)
#define GEMM_SMEM   (STAGES * STG_BYTES)

__device__ __forceinline__ uint32_t swz(int r, int c4) {
    return (uint32_t)(r * 64 + ((c4 ^ ((r >> 1) & 3)) << 4));
}

template<bool GUARD_N>
__global__ __launch_bounds__(256, 2) void gemm_mma(
    const __nv_bfloat16* __restrict__ Ah, const __nv_bfloat16* __restrict__ Al,
    const __nv_bfloat16* __restrict__ Bh, const __nv_bfloat16* __restrict__ Bl,
    float* __restrict__ C, int M, int Nn, int Kk, int ldc)
{
    extern __shared__ char smem[];
    const uint32_t sb = smem_u32(smem);
    const int tid = threadIdx.x;
    const int wid = tid >> 5;
    const int lid = tid & 31;
    const int warp_m = wid & 3;
    const int warp_n = wid >> 2;
    const int m0 = blockIdx.x * 128;
    const int n0 = blockIdx.y * 128;

    const __nv_bfloat16* srcs[4] = {Ah, Al, Bh, Bl};

    float acc[2][8][4];
#pragma unroll
    for (int i = 0; i < 2; i++)
#pragma unroll
        for (int j = 0; j < 8; j++)
#pragma unroll
            for (int q = 0; q < 4; q++) acc[i][j][q] = 0.f;

    const int KT = Kk / BK;
    const int id0 = tid, id1 = tid + 256;
    const int r0i = id0 >> 2, c40 = id0 & 3;
    const int r1i = id1 >> 2, c41 = id1 & 3;

    auto load_stage = [&](int s, int kt) {
        const uint32_t stg = sb + s * STG_BYTES;
        const size_t kb = (size_t)(kt * BK) * 2;
#pragma unroll
        for (int arr = 0; arr < 4; arr++) {
            const char* base = (const char*)srcs[arr];
            const int rbase = (arr < 2) ? m0 : n0;
            int gr0 = rbase + r0i, gr1 = rbase + r1i;
            if (GUARD_N && arr >= 2) {
                gr0 = (gr0 < Nn) ? gr0 : (Nn - 1);
                gr1 = (gr1 < Nn) ? gr1 : (Nn - 1);
            }
            CP_ASYNC16(stg + arr * ARR_BYTES + swz(r0i, c40),
                       base + (size_t)gr0 * Kk * 2 + kb + c40 * 16);
            CP_ASYNC16(stg + arr * ARR_BYTES + swz(r1i, c41),
                       base + (size_t)gr1 * Kk * 2 + kb + c41 * 16);
        }
    };

    load_stage(0, 0); CP_COMMIT();
    load_stage(1, 1); CP_COMMIT();

    const int rowin = lid & 7;
    const int mat   = lid >> 3;

    for (int kt = 0; kt < KT; kt++) {
        CP_WAIT(STAGES - 2);
        __syncthreads();

        const uint32_t stg = sb + (kt % STAGES) * STG_BYTES;
#pragma unroll
        for (int ks = 0; ks < 2; ks++) {
            uint32_t afr[2][2][4];
#pragma unroll
            for (int split = 0; split < 2; split++)
#pragma unroll
                for (int mt = 0; mt < 2; mt++) {
                    int r  = warp_m * 32 + mt * 16 + rowin + ((mat & 1) << 3);
                    int c4 = ks * 2 + (mat >> 1);
                    ldsm_x4(afr[split][mt], stg + split * ARR_BYTES + swz(r, c4));
                }
            uint32_t bfr[2][8][2];
#pragma unroll
            for (int split = 0; split < 2; split++)
#pragma unroll
                for (int ntp = 0; ntp < 4; ntp++) {
                    int n  = warp_n * 64 + ntp * 16 + rowin + ((mat >> 1) << 3);
                    int c4 = ks * 2 + (mat & 1);
                    uint32_t t[4];
                    ldsm_x4(t, stg + (2 + split) * ARR_BYTES + swz(n, c4));
                    bfr[split][ntp * 2][0]     = t[0];
                    bfr[split][ntp * 2][1]     = t[1];
                    bfr[split][ntp * 2 + 1][0] = t[2];
                    bfr[split][ntp * 2 + 1][1] = t[3];
                }
#pragma unroll
            for (int mt = 0; mt < 2; mt++)
#pragma unroll
                for (int nt = 0; nt < 8; nt++) {
                    mma_bf16(acc[mt][nt], afr[0][mt], bfr[0][nt]);
                    mma_bf16(acc[mt][nt], afr[0][mt], bfr[1][nt]);
                    mma_bf16(acc[mt][nt], afr[1][mt], bfr[0][nt]);
                }
        }

        const int knext = kt + STAGES - 1;
        if (knext < KT) load_stage(knext % STAGES, knext);
        CP_COMMIT();
    }

    const int gq  = lid >> 2;
    const int ln2 = (lid & 3) * 2;
#pragma unroll
    for (int mt = 0; mt < 2; mt++) {
        const int m = m0 + warp_m * 32 + mt * 16 + gq;
#pragma unroll
        for (int nt = 0; nt < 8; nt++) {
            const int n = n0 + warp_n * 64 + nt * 8 + ln2;
            if (!GUARD_N || n < Nn) {
                *(float2*)(C + (size_t)m * ldc + n) =
                    make_float2(acc[mt][nt][0], acc[mt][nt][1]);
                *(float2*)(C + (size_t)(m + 8) * ldc + n) =
                    make_float2(acc[mt][nt][2], acc[mt][nt][3]);
            }
        }
    }
}

// ---------------- bf16 hi/lo split conversion ----------------
__global__ __launch_bounds__(256) void split_bf16(const float* __restrict__ x,
                                                  __nv_bfloat16* __restrict__ h,
                                                  __nv_bfloat16* __restrict__ l,
                                                  size_t n4)
{
    size_t i = (size_t)blockIdx.x * 256 + threadIdx.x;
    if (i >= n4) return;
    float4 v = *(const float4*)(x + i * 4);
    __nv_bfloat16 h0 = __float2bfloat16(v.x), h1 = __float2bfloat16(v.y);
    __nv_bfloat16 h2 = __float2bfloat16(v.z), h3 = __float2bfloat16(v.w);
    __nv_bfloat16 l0 = __float2bfloat16(v.x - __bfloat162float(h0));
    __nv_bfloat16 l1 = __float2bfloat16(v.y - __bfloat162float(h1));
    __nv_bfloat16 l2 = __float2bfloat16(v.z - __bfloat162float(h2));
    __nv_bfloat16 l3 = __float2bfloat16(v.w - __bfloat162float(h3));
    __nv_bfloat162* hp = (__nv_bfloat162*)(h + i * 4);
    __nv_bfloat162* lp = (__nv_bfloat162*)(l + i * 4);
    hp[0] = __nv_bfloat162(h0, h1); hp[1] = __nv_bfloat162(h2, h3);
    lp[0] = __nv_bfloat162(l0, l1); lp[1] = __nv_bfloat162(l2, l3);
}

// ---------------- depthwise causal conv (K=4) + SiLU ----------------
__global__ __launch_bounds__(256) void conv_silu_kernel(const float* __restrict__ cw,
                                                        const float* __restrict__ cb)
{
    int c = blockIdx.x * 256 + threadIdx.x;
    int s = blockIdx.y;
    int b = blockIdx.z;
    float w0 = cw[c * 4 + 0], w1 = cw[c * 4 + 1], w2 = cw[c * 4 + 2], w3 = cw[c * 4 + 3];
    const float* base = g_proj + (size_t)(b * SEQ) * PROJD + IDIM + c;
    float acc = cb[c];
    if (s >= 3) acc = fmaf(base[(size_t)(s - 3) * PROJD], w0, acc);
    if (s >= 2) acc = fmaf(base[(size_t)(s - 2) * PROJD], w1, acc);
    if (s >= 1) acc = fmaf(base[(size_t)(s - 1) * PROJD], w2, acc);
    acc = fmaf(base[(size_t)s * PROJD], w3, acc);
    acc = acc / (1.f + expf(-acc));
    g_conv[(size_t)(b * SEQ + s) * CONVD + c] = acc;
}

// ---------------- dt/dA ----------------
__global__ __launch_bounds__(256) void dt_kernel(const float* __restrict__ dt_bias,
                                                 const float* __restrict__ A_log)
{
    int idx = blockIdx.x * 256 + threadIdx.x;
    int h = idx & (NHEADS - 1);
    int bs = idx >> 6;
    float v = g_proj[(size_t)bs * PROJD + IDIM + CONVD + h] + dt_bias[h];
    float sp = (v > 20.f) ? v : log1pf(expf(v));
    sp = fminf(fmaxf(sp, 0.f), 1e9f);
    g_dt[idx] = sp;
    g_dA[idx] = expf(-expf(A_log[h]) * sp);
}

// ---------------- sequential selective scan (pipelined loads + pipelined reduce) ----
#define NSTG   8
#define SGF    336
#define OFF_B  0
#define OFF_C  128
#define OFF_X  256
#define OFF_M  320

__global__ __launch_bounds__(512) void scan_kernel(const float* __restrict__ Dp)
{
    __shared__ __align__(16) float sbuf[NSTG * SGF];
    __shared__ float red[2][8][72];

    const int b   = blockIdx.x >> 6;
    const int h   = blockIdx.x & 63;
    const int tid = threadIdx.x;
    const int p   = tid & 63;
    const int ng  = tid >> 6;          // 0..7, uniform per warp
    const int n0  = ng * 16;

    const float* convb = g_conv + (size_t)b * SEQ * CONVD;
    const float* dtp   = g_dt  + (size_t)b * SEQ * NHEADS + h;
    const float* dAp   = g_dA  + (size_t)b * SEQ * NHEADS + h;
    float*       yb    = g_y   + (size_t)b * SEQ * IDIM + h * PDIM;
    const uint32_t sb  = smem_u32(sbuf);

    auto fill = [&](int s, int t) {
        if (t < SEQ) {
            const float* row = convb + (size_t)t * CONVD;
            const uint32_t dst = sb + (uint32_t)(s * SGF) * 4;
            if (tid < 32) {
                CP_ASYNC16(dst + OFF_B * 4 + tid * 16, row + IDIM + tid * 4);
            } else if (tid < 64) {
                CP_ASYNC16(dst + OFF_C * 4 + (tid - 32) * 16, row + IDIM + NDIM + (tid - 32) * 4);
            } else if (tid < 80) {
                CP_ASYNC16(dst + OFF_X * 4 + (tid - 64) * 16, row + h * PDIM + (tid - 64) * 4);
            } else if (tid == 80) {
                CP_ASYNC4(dst + (OFF_M + 0) * 4, dAp + (size_t)t * NHEADS);
            } else if (tid == 81) {
                CP_ASYNC4(dst + (OFF_M + 1) * 4, dtp + (size_t)t * NHEADS);
            }
        }
    };

#pragma unroll
    for (int i = 0; i < NSTG - 1; i++) { fill(i, i); CP_COMMIT(); }

    const float Dh = Dp[h];
    float st[16];
#pragma unroll
    for (int j = 0; j < 16; j++) st[j] = 0.f;
    float x_prev = 0.f;

    for (int t = 0; t < SEQ; t++) {
        CP_WAIT(NSTG - 2);
        __syncthreads();

        if (t > 0 && tid < 64) {
            const float (*rp)[72] = red[(t - 1) & 1];
            float s = rp[0][tid] + rp[1][tid] + rp[2][tid] + rp[3][tid]
                    + rp[4][tid] + rp[5][tid] + rp[6][tid] + rp[7][tid];
            yb[(size_t)(t - 1) * IDIM + tid] = fmaf(Dh, x_prev, s);
        }

        fill((t + NSTG - 1) % NSTG, t + NSTG - 1);
        CP_COMMIT();

        const float* stg = sbuf + (t % NSTG) * SGF;
        const float dAv = stg[OFF_M + 0];
        const float dtv = stg[OFF_M + 1];
        const float xv  = stg[OFF_X + p];
        const float coef = dtv * xv;
        x_prev = xv;

        float acc = 0.f;
#pragma unroll
        for (int q = 0; q < 4; q++) {
            float4 B4 = *(const float4*)(stg + OFF_B + n0 + q * 4);
            float4 C4 = *(const float4*)(stg + OFF_C + n0 + q * 4);
            float* s4 = st + q * 4;
            s4[0] = fmaf(s4[0], dAv, coef * B4.x);
            s4[1] = fmaf(s4[1], dAv, coef * B4.y);
            s4[2] = fmaf(s4[2], dAv, coef * B4.z);
            s4[3] = fmaf(s4[3], dAv, coef * B4.w);
            acc = fmaf(s4[0], C4.x, acc);
            acc = fmaf(s4[1], C4.y, acc);
            acc = fmaf(s4[2], C4.z, acc);
            acc = fmaf(s4[3], C4.w, acc);
        }
        red[t & 1][ng][p] = acc;
    }

    __syncthreads();
    if (tid < 64) {
        const float (*rp)[72] = red[(SEQ - 1) & 1];
        float s = rp[0][tid] + rp[1][tid] + rp[2][tid] + rp[3][tid]
                + rp[4][tid] + rp[5][tid] + rp[6][tid] + rp[7][tid];
        yb[(size_t)(SEQ - 1) * IDIM + tid] = fmaf(Dh, x_prev, s);
    }
}

// ---------------- y*silu(gate), RMSNorm, fused bf16 split ----------------
__global__ __launch_bounds__(256) void gate_norm_kernel(const float* __restrict__ norm_w)
{
    int bs = blockIdx.x;
    const float* gp   = g_proj + (size_t)bs * PROJD;
    const float* yrow = g_y    + (size_t)bs * IDIM;
    __nv_bfloat16* oh = g_yn_h + (size_t)bs * IDIM;
    __nv_bfloat16* ol = g_yn_l + (size_t)bs * IDIM;

    float v[16];
    float ss = 0.f;
#pragma unroll
    for (int i = 0; i < 16; i++) {
        int idx = threadIdx.x + i * 256;
        float gate = gp[idx];
        float sil = gate / (1.f + expf(-gate));
        float val = yrow[idx] * sil;
        v[i] = val;
        ss = fmaf(val, val, ss);
    }
#pragma unroll
    for (int off = 16; off; off >>= 1) ss += __shfl_xor_sync(0xffffffffu, ss, off);
    __shared__ float red[8];
    if ((threadIdx.x & 31) == 0) red[threadIdx.x >> 5] = ss;
    __syncthreads();
    float tot = 0.f;
#pragma unroll
    for (int w = 0; w < 8; w++) tot += red[w];
    float scale = rsqrtf(tot * (1.f / IDIM) + 1e-6f);
#pragma unroll
    for (int i = 0; i < 16; i++) {
        int idx = threadIdx.x + i * 256;
        float val = v[i] * scale * norm_w[idx];
        __nv_bfloat16 hb = __float2bfloat16(val);
        oh[idx] = hb;
        ol[idx] = __float2bfloat16(val - __bfloat162float(hb));
    }
}

// ---------------- launch ----------------
extern "C" void kernel_launch(void* const* d_in, const int* in_sizes, int n_in,
                              void* d_out, int out_size)
{
    const float* hs      = (const float*)d_in[0];
    const float* w_in    = (const float*)d_in[2];
    const float* conv_w  = (const float*)d_in[3];
    const float* conv_b  = (const float*)d_in[4];
    const float* dt_bias = (const float*)d_in[5];
    const float* A_log   = (const float*)d_in[6];
    const float* Dp      = (const float*)d_in[7];
    const float* norm_w  = (const float*)d_in[8];
    const float* w_out   = (const float*)d_in[9];
    float* out = (float*)d_out;

    float *proj;
    __nv_bfloat16 *hs_h, *hs_l, *win_h, *win_l, *yn_h, *yn_l, *wo_h, *wo_l;
    cudaGetSymbolAddress((void**)&proj,  g_proj);
    cudaGetSymbolAddress((void**)&hs_h,  g_hs_h);
    cudaGetSymbolAddress((void**)&hs_l,  g_hs_l);
    cudaGetSymbolAddress((void**)&win_h, g_win_h);
    cudaGetSymbolAddress((void**)&win_l, g_win_l);
    cudaGetSymbolAddress((void**)&yn_h,  g_yn_h);
    cudaGetSymbolAddress((void**)&yn_l,  g_yn_l);
    cudaGetSymbolAddress((void**)&wo_h,  g_wo_h);
    cudaGetSymbolAddress((void**)&wo_l,  g_wo_l);

    cudaFuncSetAttribute(gemm_mma<true>,
                         cudaFuncAttributeMaxDynamicSharedMemorySize, GEMM_SMEM);
    cudaFuncSetAttribute(gemm_mma<false>,
                         cudaFuncAttributeMaxDynamicSharedMemorySize, GEMM_SMEM);

    // fork-join resources (created per call; kernel_launch runs only a few times,
    // graph replays do not re-enter this function)
    cudaStream_t s1;
    cudaStreamCreateWithFlags(&s1, cudaStreamNonBlocking);
    cudaEvent_t evSplit, evB;
    cudaEventCreateWithFlags(&evSplit, cudaEventDisableTiming);
    cudaEventCreateWithFlags(&evB,     cudaEventDisableTiming);

    // stream 0: operand splits needed by GEMM1
    {
        size_t n4;
        n4 = (size_t)MROWS * HIDDEN / 4;
        split_bf16<<<(unsigned)((n4 + 255) / 256), 256>>>(hs, hs_h, hs_l, n4);
        n4 = (size_t)PROJD * HIDDEN / 4;
        split_bf16<<<(unsigned)((n4 + 255) / 256), 256>>>(w_in, win_h, win_l, n4);
    }
    cudaEventRecord(evSplit, 0);

    // stream s1 (forked): w_out split + gate-part GEMM1b (cols 0..4095)
    cudaStreamWaitEvent(s1, evSplit, 0);
    {
        size_t n4 = (size_t)HIDDEN * IDIM / 4;
        split_bf16<<<(unsigned)((n4 + 255) / 256), 256, 0, s1>>>(w_out, wo_h, wo_l, n4);
    }
    {
        dim3 g1b(MROWS / 128, IDIM / 128);          // 32 x 32
        gemm_mma<false><<<g1b, 256, GEMM_SMEM, s1>>>(hs_h, hs_l, win_h, win_l,
                                                     proj, MROWS, IDIM, HIDDEN, PROJD);
    }
    cudaEventRecord(evB, s1);

    // stream 0: scan-path GEMM1a (cols 4096..8511) -> conv -> dt -> scan
    {
        const int NA = PROJD - IDIM;                // 4416
        dim3 g1a(MROWS / 128, (NA + 127) / 128);    // 32 x 35
        gemm_mma<true><<<g1a, 256, GEMM_SMEM>>>(hs_h, hs_l,
                                                win_h + (size_t)IDIM * HIDDEN,
                                                win_l + (size_t)IDIM * HIDDEN,
                                                proj + IDIM, MROWS, NA, HIDDEN, PROJD);
    }
    conv_silu_kernel<<<dim3(CONVD / 256, SEQ, BATCH), 256>>>(conv_w, conv_b);
    dt_kernel<<<(MROWS * NHEADS) / 256, 256>>>(dt_bias, A_log);
    scan_kernel<<<BATCH * NHEADS, 512>>>(Dp);

    // join: gate_norm needs gate (s1) + y (stream 0)
    cudaStreamWaitEvent(0, evB, 0);
    gate_norm_kernel<<<MROWS, 256>>>(norm_w);

    // out-projection (M=4096, N=2048, K=4096)
    dim3 g2(MROWS / 128, HIDDEN / 128);
    gemm_mma<false><<<g2, 256, GEMM_SMEM>>>(yn_h, yn_l, wo_h, wo_l,
                                            out, MROWS, HIDDEN, IDIM, HIDDEN);
}